// round 3
// baseline (speedup 1.0000x reference)
#include <cuda_runtime.h>
#include <cstdint>

// DiagonalSISOCell: V=100000, D=64, N=16
// out[v,d,q] = sum_n ( exp(delta_v*A[d,n])*state[v,d,n] + delta_v*B[d,n]*x[v,d] ) * C[d,n,q]
// delta_v = softplus(x[v,:] @ w_delta + b_delta)

#define V_TOK 100000
#define LOG2E 1.4426950408889634f

// padded so bulk-copy of delta rows can over-read by <64B
__device__ float g_delta[100096];

// ---- smem layout (floats), 64-token tiles, 4 d's per block -----------------
#define PITCH   68                    // 272B rows: conflict-free LDS.128 phases
#define TILE_F  (64 * PITCH)          // 4352
#define OFF_C     0                   // C_s[4][16][16]      (1024)
#define OFF_AB    1024                // AB_s[4][16] float2  (128)
#define OFF_IN    1152                // in_t[2][TILE_F]
#define OFF_OUT   (1152 + 2*TILE_F)   // out_t[TILE_F]
#define OFF_X     (OFF_OUT + TILE_F)  // x_s[2][64*4]
#define OFF_DELTA (OFF_X + 512)       // delta_s[2][64]
#define SMEM_FLOATS (OFF_DELTA + 128) // 14848 floats = 59392 B

// ---------------------------------------------------------------------------
__device__ __forceinline__ float2 ffma2(float2 a, float2 b, float2 c) {
    float2 r;
    asm("fma.rn.f32x2 %0, %1, %2, %3;"
        : "=l"(*reinterpret_cast<unsigned long long*>(&r))
        : "l"(*reinterpret_cast<unsigned long long*>(&a)),
          "l"(*reinterpret_cast<unsigned long long*>(&b)),
          "l"(*reinterpret_cast<unsigned long long*>(&c)));
    return r;
}
__device__ __forceinline__ float ex2_approx(float x) {
    float r; asm("ex2.approx.f32 %0, %1;" : "=f"(r) : "f"(x)); return r;
}
__device__ __forceinline__ uint32_t smem_u32(const void* p) {
    uint32_t a;
    asm("{ .reg .u64 t; cvta.to.shared.u64 t, %1; cvt.u32.u64 %0, t; }"
        : "=r"(a) : "l"(p));
    return a;
}
__device__ __forceinline__ void bulk_g2s(uint32_t dst, const void* src,
                                         uint32_t bytes, uint32_t mbar) {
    asm volatile(
        "cp.async.bulk.shared::cluster.global.mbarrier::complete_tx::bytes "
        "[%0], [%1], %2, [%3];"
        :: "r"(dst), "l"(src), "r"(bytes), "r"(mbar) : "memory");
}
__device__ __forceinline__ void bulk_s2g(void* dst, uint32_t src, uint32_t bytes) {
    asm volatile("cp.async.bulk.global.shared::cta.bulk_group [%0], [%1], %2;"
                 :: "l"(dst), "r"(src), "r"(bytes) : "memory");
}
__device__ __forceinline__ void mbar_init(uint32_t mbar, uint32_t cnt) {
    asm volatile("mbarrier.init.shared.b64 [%0], %1;" :: "r"(mbar), "r"(cnt) : "memory");
}
__device__ __forceinline__ void mbar_arrive_tx(uint32_t mbar, uint32_t bytes) {
    asm volatile("mbarrier.arrive.expect_tx.shared.b64 _, [%0], %1;"
                 :: "r"(mbar), "r"(bytes) : "memory");
}
__device__ __forceinline__ void mbar_arrive(uint32_t mbar) {
    asm volatile("mbarrier.arrive.shared.b64 _, [%0];" :: "r"(mbar) : "memory");
}
__device__ __forceinline__ void mbar_wait(uint32_t mbar, uint32_t parity) {
    asm volatile(
        "{\n\t.reg .pred P;\n\t"
        "W_%=:\n\t"
        "mbarrier.try_wait.parity.acquire.cta.shared::cta.b64 P, [%0], %1, 0x989680;\n\t"
        "@!P bra W_%=;\n\t}"
        :: "r"(mbar), "r"(parity) : "memory");
}
__device__ __forceinline__ void bulk_commit() {
    asm volatile("cp.async.bulk.commit_group;" ::: "memory");
}
__device__ __forceinline__ void bulk_wait0() {
    asm volatile("cp.async.bulk.wait_group 0;" ::: "memory");
}
__device__ __forceinline__ void fence_async() {
    asm volatile("fence.proxy.async.shared::cta;" ::: "memory");
}

// ---------------------------------------------------------------------------
// Kernel 1: delta[v] = softplus(dot(x[v,:], w) + b). One warp per token row.
// ---------------------------------------------------------------------------
__global__ void delta_kernel(const float* __restrict__ x,
                             const float* __restrict__ w,
                             const float* __restrict__ b)
{
    int warp = (blockIdx.x * blockDim.x + threadIdx.x) >> 5;
    int lane = threadIdx.x & 31;
    if (warp >= V_TOK) return;

    const float* xr = x + warp * 64;
    float s = xr[lane] * w[lane] + xr[lane + 32] * w[lane + 32];
#pragma unroll
    for (int o = 16; o > 0; o >>= 1)
        s += __shfl_xor_sync(0xffffffffu, s, o);

    if (lane == 0) {
        float t = s + b[0];
        g_delta[warp] = fmaxf(t, 0.0f) + log1pf(expf(-fabsf(t)));
    }
}

// ---------------------------------------------------------------------------
// Kernel 2: bulk-DMA double-buffered main kernel.
// Block = 128 thr = 4 warps, warp w owns d = grp*4 + w. A block-tile is 64
// tokens: input rows state[v, grp*4.. +4, :] = 256B contiguous -> one
// cp.async.bulk per row into a pitch-272B smem tile (same for x 16B rows and
// delta). Compute is shuffle-free register FFMA2 contraction. Output rows are
// assembled in smem and written back with cp.async.bulk shared->global.
// ---------------------------------------------------------------------------
__global__ void __launch_bounds__(128, 3)
siso_kernel(const float* __restrict__ x,
            const float* __restrict__ state,
            const float* __restrict__ log_nA,
            const float* __restrict__ Bm,
            const float* __restrict__ Cm,
            float* __restrict__ out)
{
    extern __shared__ float sm[];
    __shared__ __align__(8) unsigned long long mbar_store[2];

    const int tid = threadIdx.x;
    const int w   = tid >> 5;
    const int l   = tid & 31;
    const int grp = blockIdx.x & 15;      // 16 d-groups of 4
    const int chunk = blockIdx.x >> 4;    // 28 token chunks

    const uint32_t smb = smem_u32(sm);
    const uint32_t mb0 = smem_u32(&mbar_store[0]);
    const uint32_t mb1 = smem_u32(&mbar_store[1]);

    if (tid == 0) { mbar_init(mb0, 64); mbar_init(mb1, 64); }

    // stage C slice + (A*log2e, B) pairs
    {
        const float* src = Cm + grp * 4 * 256;
        for (int i = tid; i < 1024; i += 128) sm[OFF_C + i] = src[i];
        if (tid < 64) {
            int dl = tid >> 4, n = tid & 15;
            int gd = grp * 4 + dl;
            float A2 = -__expf(log_nA[gd * 16 + n]) * LOG2E;
            float2* AB = reinterpret_cast<float2*>(sm + OFF_AB);
            AB[dl * 16 + n] = make_float2(A2, Bm[gd * 16 + n]);
        }
    }
    __syncthreads();   // mbar init + C/AB visible

    const int v_base  = chunk * 3584;
    const int v_end   = min(V_TOK, v_base + 3584);
    const int n_tiles = (v_end - v_base + 63) >> 6;

    // --- issue input DMA for tile ti into buffer b (threads 0..63 only) ----
    auto issue = [&](int ti, int b) {
        const int v0 = v_base + ti * 64;
        const int nt = min(64, v_end - v0);
        const uint32_t mb = b ? mb1 : mb0;
        const int t = tid;
        if (t < nt) {
            uint32_t dpad = (uint32_t)(((nt * 4) + 15) & ~15);
            uint32_t bytes = 256 + 16 + (t == 0 ? dpad : 0);
            mbar_arrive_tx(mb, bytes);
            bulk_g2s(smb + (OFF_IN + b * TILE_F + t * PITCH) * 4,
                     state + (size_t)(v0 + t) * 1024 + grp * 64, 256, mb);
            bulk_g2s(smb + (OFF_X + b * 256 + t * 4) * 4,
                     x + (size_t)(v0 + t) * 64 + grp * 4, 16, mb);
            if (t == 0)
                bulk_g2s(smb + (OFF_DELTA + b * 64) * 4, g_delta + v0, dpad, mb);
        } else {
            mbar_arrive(mb);
        }
    };

    // prologue: fill both buffers
    if (tid < 64) {
        issue(0, 0);
        if (n_tiles > 1) issue(1, 1);
    }

    const float*  Cw  = sm + OFF_C + w * 256;
    const float2* ABw = reinterpret_cast<const float2*>(sm + OFF_AB) + w * 16;

    for (int i = 0; i < n_tiles; i++) {
        const int b  = i & 1;
        const int ph = (i >> 1) & 1;
        const int v0 = v_base + i * 64;
        const int nt = min(64, v_end - v0);

        mbar_wait(b ? mb1 : mb0, ph);

        // ---- compute: lane owns tokens l and l+32 --------------------------
        const float* in_t = sm + OFF_IN + b * TILE_F;
        const float delta_a = sm[OFF_DELTA + b * 64 + l];
        const float delta_c = sm[OFF_DELTA + b * 64 + l + 32];
        const float x_a = sm[OFF_X + b * 256 + l * 4 + w];
        const float x_c = sm[OFF_X + b * 256 + (l + 32) * 4 + w];
        const float dx_a = delta_a * x_a;
        const float dx_c = delta_c * x_c;

        const float* ra = in_t + l * PITCH + w * 16;
        const float* rb = in_t + (l + 32) * PITCH + w * 16;

        float2 acc_a[8], acc_c[8];
#pragma unroll
        for (int p = 0; p < 8; p++) {
            acc_a[p] = make_float2(0.f, 0.f);
            acc_c[p] = make_float2(0.f, 0.f);
        }

        float4 s4a, s4b;
#pragma unroll
        for (int n = 0; n < 16; n++) {
            if ((n & 3) == 0) {
                s4a = *reinterpret_cast<const float4*>(ra + n);
                s4b = *reinterpret_cast<const float4*>(rb + n);
            }
            float s_a = (n & 3) == 0 ? s4a.x : (n & 3) == 1 ? s4a.y : (n & 3) == 2 ? s4a.z : s4a.w;
            float s_c = (n & 3) == 0 ? s4b.x : (n & 3) == 1 ? s4b.y : (n & 3) == 2 ? s4b.z : s4b.w;

            float2 ab = ABw[n];
            float e_a = ex2_approx(delta_a * ab.x);
            float e_c = ex2_approx(delta_c * ab.x);
            float nv_a = fmaf(e_a, s_a, dx_a * ab.y);
            float nv_c = fmaf(e_c, s_c, dx_c * ab.y);
            float2 va = make_float2(nv_a, nv_a);
            float2 vc = make_float2(nv_c, nv_c);

            const float4* crow = reinterpret_cast<const float4*>(Cw + n * 16);
#pragma unroll
            for (int p4 = 0; p4 < 4; p4++) {
                float4 c4 = crow[p4];                    // broadcast LDS.128
                float2 c01 = make_float2(c4.x, c4.y);
                float2 c23 = make_float2(c4.z, c4.w);
                acc_a[2 * p4]     = ffma2(va, c01, acc_a[2 * p4]);
                acc_a[2 * p4 + 1] = ffma2(va, c23, acc_a[2 * p4 + 1]);
                acc_c[2 * p4]     = ffma2(vc, c01, acc_c[2 * p4]);
                acc_c[2 * p4 + 1] = ffma2(vc, c23, acc_c[2 * p4 + 1]);
            }
        }

        // ---- drain previous store, then refill this input buffer ----------
        if (i > 0 && tid < 64) bulk_wait0();
        __syncthreads();   // all reads of in_t[b]/out_t done; store drained

        if (i + 2 < n_tiles && tid < 64) issue(i + 2, b);

        // ---- assemble output rows in smem ----------------------------------
        float* oa = sm + OFF_OUT + l * PITCH + w * 16;
        float* oc = sm + OFF_OUT + (l + 32) * PITCH + w * 16;
#pragma unroll
        for (int p4 = 0; p4 < 4; p4++) {
            *reinterpret_cast<float4*>(oa + 4 * p4) =
                make_float4(acc_a[2 * p4].x, acc_a[2 * p4].y,
                            acc_a[2 * p4 + 1].x, acc_a[2 * p4 + 1].y);
            *reinterpret_cast<float4*>(oc + 4 * p4) =
                make_float4(acc_c[2 * p4].x, acc_c[2 * p4].y,
                            acc_c[2 * p4 + 1].x, acc_c[2 * p4 + 1].y);
        }
        __syncthreads();

        // ---- bulk store: one 256B row per thread ---------------------------
        if (tid < 64) {
            fence_async();
            if (tid < nt)
                bulk_s2g(out + (size_t)(v0 + tid) * 1024 + grp * 64,
                         smb + (OFF_OUT + tid * PITCH) * 4, 256);
            bulk_commit();
        }
    }

    if (tid < 64) bulk_wait0();
}

// ---------------------------------------------------------------------------
// Launch
// ---------------------------------------------------------------------------
extern "C" void kernel_launch(void* const* d_in, const int* in_sizes, int n_in,
                              void* d_out, int out_size)
{
    const float* x       = (const float*)d_in[0];  // [V, D]
    const float* state   = (const float*)d_in[1];  // [V, D, N]
    const float* log_nA  = (const float*)d_in[2];  // [D, N]
    const float* B       = (const float*)d_in[3];  // [D, N]
    const float* C       = (const float*)d_in[4];  // [D, N, N]
    const float* w_delta = (const float*)d_in[5];  // [1, D]
    const float* b_delta = (const float*)d_in[6];  // [1]
    float* out = (float*)d_out;                    // [V, D, N]

    delta_kernel<<<(V_TOK + 7) / 8, 256>>>(x, w_delta, b_delta);

    const int smem_bytes = SMEM_FLOATS * 4;        // 59392 B
    cudaFuncSetAttribute(siso_kernel,
                         cudaFuncAttributeMaxDynamicSharedMemorySize, smem_bytes);
    // 16 d-groups x 28 chunks = 448 blocks (~3/SM)
    siso_kernel<<<448, 128, smem_bytes>>>(x, state, log_nA, B, C, out);
}